// round 12
// baseline (speedup 1.0000x reference)
#include <cuda_runtime.h>
#include <cstdint>
#include <cstddef>

// Neural-CDE forward, R12 = R11 plus:
//  (a) fast lipswish: __fdividef (MUFU.RCP) instead of full-precision fp32
//      division — removes the Newton-refinement FMAs from the critical
//      combine chain of all 12 lipswish phases per step;
//  (b) GROUP-LOCAL projection: each group's proj partial covers only its own
//      32 H-dims (= the bufA columns it writes itself), so the stage-3-end
//      full barrier becomes a group bar.sync; proj partials are reduced by
//      128 threads after the existing st0/l0 deposit barrier.
// Config unchanged: 128 CTAs x 512 thr, MC=8, 8-way split-K, 4 cols/thread,
// fma.rn.f32x2 GEMM core, exact weight loads, cross-GEMM weight prefetch,
// group-local act-ready barriers, packed-f32x2 tree combine.

#define T_N   128
#define IN_N  32
#define H_N   256
#define OUT_N 32
#define MC    8            // batch rows per CTA
#define BST   8            // activation buffer stride [dim][row]
#define NTH   512
#define NG    8            // split-K groups
#define NCT   64           // column-threads per group (4 cols each)
#define KSH   (H_N / NG)   // 32
#define KSI   (IN_N / NG)  // 4
#define RST   36           // reduction stride in floats (32 data + 4 pad)

#define BUF_FLOATS   (H_N * BST)            // 2048
#define RED_FLOATS   (NG * NCT * RST)       // 18432
#define SCR_U64      (NG * 128)             // proj partials: 8 groups x 128 units
#define SMEM_FLOATS  (2 * BUF_FLOATS + RED_FLOATS + 2 * SCR_U64)
#define SMEM_BYTES   (SMEM_FLOATS * 4)      // 98304

typedef unsigned long long u64;

__device__ __forceinline__ u64 fma2(u64 a, u64 b, u64 c) {
    u64 d;
    asm("fma.rn.f32x2 %0, %1, %2, %3;" : "=l"(d) : "l"(a), "l"(b), "l"(c));
    return d;
}
__device__ __forceinline__ u64 add2(u64 a, u64 b) {
    u64 d;
    asm("add.rn.f32x2 %0, %1, %2;" : "=l"(d) : "l"(a), "l"(b));
    return d;
}
__device__ __forceinline__ u64 dup2(float x) {
    u64 d; unsigned int u = __float_as_uint(x);
    asm("mov.b64 %0, {%1, %2};" : "=l"(d) : "r"(u), "r"(u));
    return d;
}
__device__ __forceinline__ float2 unpk(u64 v) {
    unsigned int a, b;
    asm("mov.b64 {%0, %1}, %2;" : "=r"(a), "=r"(b) : "l"(v));
    return make_float2(__uint_as_float(a), __uint_as_float(b));
}
__device__ __forceinline__ float lipswish(float x) {
    // 0.909*x*sigmoid(x); __fdividef -> MUFU.RCP (2-ulp, huge headroom vs 1e-3)
    return __fdividef(0.909f * x, 1.0f + __expf(-x));
}
// 64-thread named barrier for split-K group kg (ids 1..8; 0 = __syncthreads).
__device__ __forceinline__ void gbar(int kg) {
    asm volatile("bar.sync %0, %1;" :: "r"(1 + kg), "r"(64) : "memory");
}

// Preload the first two 4-k-row weight blocks of a GEMM (guards compile out).
template <int KS>
__device__ __forceinline__ void wpre(const float* __restrict__ Wp,
                                     float4* __restrict__ wA,
                                     float4* __restrict__ wB)
{
#pragma unroll
    for (int j = 0; j < 4; j++) if (j < KS)     wA[j] = *(const float4*)(Wp + j * H_N);
#pragma unroll
    for (int j = 0; j < 4; j++) if (4 + j < KS) wB[j] = *(const float4*)(Wp + (4 + j) * H_N);
}

// Raw partial GEMM over KS k-rows, 4 columns, 8 rows. acc[c*4+p] packs rows
// (2p,2p+1) of local column c: p=0 -> ua.x, p=1 -> ua.y, p=2 -> ub.x,
// p=3 -> ub.y. Wp pre-offset to (koff, n0); bp pre-offset to koff. wA/wB hold
// the first two blocks (preloaded by caller before the previous barrier).
template <int KS>
__device__ __forceinline__ void gemmT4(const float* __restrict__ Wp,
                                       const float* __restrict__ bp,
                                       float4* __restrict__ wA,
                                       float4* __restrict__ wB,
                                       u64* __restrict__ acc)
{
#pragma unroll
    for (int i = 0; i < 16; i++) acc[i] = 0ull;

    ulonglong2 ua = *(const ulonglong2*)(bp);       // k-row 0: rows (0,1),(2,3)
    ulonglong2 ub = *(const ulonglong2*)(bp + 4);   //          rows (4,5),(6,7)

#pragma unroll
    for (int kb = 0; kb < KS; kb += 4) {
        float4 wN[4];
        const bool ldw = (kb + 8 < KS);
        if (ldw) {
#pragma unroll
            for (int j = 0; j < 4; j++) wN[j] = *(const float4*)(Wp + (kb + 8 + j) * H_N);
        }
#pragma unroll
        for (int j = 0; j < 4; j++) {
            if (kb + j >= KS) continue;                    // compile-time (KS=4 case)
            const int knext = kb + j + 1;
            ulonglong2 na, nb;
            const bool lda = (knext < KS);
            if (lda) {
                na = *(const ulonglong2*)(bp + knext * BST);
                nb = *(const ulonglong2*)(bp + knext * BST + 4);
            }
            u64 w0 = dup2(wA[j].x), w1 = dup2(wA[j].y);
            u64 w2 = dup2(wA[j].z), w3 = dup2(wA[j].w);
            acc[0]  = fma2(ua.x, w0, acc[0]);  acc[1]  = fma2(ua.y, w0, acc[1]);
            acc[2]  = fma2(ub.x, w0, acc[2]);  acc[3]  = fma2(ub.y, w0, acc[3]);
            acc[4]  = fma2(ua.x, w1, acc[4]);  acc[5]  = fma2(ua.y, w1, acc[5]);
            acc[6]  = fma2(ub.x, w1, acc[6]);  acc[7]  = fma2(ub.y, w1, acc[7]);
            acc[8]  = fma2(ua.x, w2, acc[8]);  acc[9]  = fma2(ua.y, w2, acc[9]);
            acc[10] = fma2(ub.x, w2, acc[10]); acc[11] = fma2(ub.y, w2, acc[11]);
            acc[12] = fma2(ua.x, w3, acc[12]); acc[13] = fma2(ua.y, w3, acc[13]);
            acc[14] = fma2(ub.x, w3, acc[14]); acc[15] = fma2(ub.y, w3, acc[15]);
            if (lda) { ua = na; ub = nb; }
        }
#pragma unroll
        for (int j = 0; j < 4; j++) wA[j] = wB[j];
        if (ldw) {
#pragma unroll
            for (int j = 0; j < 4; j++) wB[j] = wN[j];
        }
    }
}

// Deposit 32 raw floats (16 packed pairs) at redp: word layout c*8+m.
__device__ __forceinline__ void red_put(float* __restrict__ redp,
                                        const u64* __restrict__ acc)
{
#pragma unroll
    for (int c = 0; c < 4; c++) {
        *(ulonglong2*)(redp + c * 8)     = make_ulonglong2(acc[c * 4],     acc[c * 4 + 1]);
        *(ulonglong2*)(redp + c * 8 + 4) = make_ulonglong2(acc[c * 4 + 2], acc[c * 4 + 3]);
    }
}

// Sum the 8 group-partials for this thread's float4 via a packed-f32x2 tree.
__device__ __forceinline__ float4 combine8(const float* __restrict__ red,
                                           int ct_e, int off)
{
    const float* p = red + ct_e * RST + off;
    ulonglong2 v0 = *(const ulonglong2*)(p);
    ulonglong2 v1 = *(const ulonglong2*)(p + 1 * NCT * RST);
    ulonglong2 v2 = *(const ulonglong2*)(p + 2 * NCT * RST);
    ulonglong2 v3 = *(const ulonglong2*)(p + 3 * NCT * RST);
    ulonglong2 v4 = *(const ulonglong2*)(p + 4 * NCT * RST);
    ulonglong2 v5 = *(const ulonglong2*)(p + 5 * NCT * RST);
    ulonglong2 v6 = *(const ulonglong2*)(p + 6 * NCT * RST);
    ulonglong2 v7 = *(const ulonglong2*)(p + 7 * NCT * RST);
    u64 ax = add2(add2(add2(v0.x, v1.x), add2(v2.x, v3.x)),
                  add2(add2(v4.x, v5.x), add2(v6.x, v7.x)));
    u64 ay = add2(add2(add2(v0.y, v1.y), add2(v2.y, v3.y)),
                  add2(add2(v4.y, v5.y), add2(v6.y, v7.y)));
    float2 lo = unpk(ax), hi = unpk(ay);
    return make_float4(lo.x, lo.y, hi.x, hi.y);
}

// GROUP-LOCAL packed projection partials: group kg covers k in
// [32kg, 32kg+32) — exactly the bufA columns group kg writes itself.
// Thread ct handles units ct and ct+64 (unit = r*16 + cp).
__device__ __forceinline__ void proj_partials(const float* __restrict__ buf,
                                              const float* __restrict__ Wd,
                                              u64* __restrict__ scr,
                                              int kg, int ct)
{
    const int kb  = kg * KSH;
    const int r1  = ct >> 4,       cp1 = ct & 15;
    const int r2  = 4 + (ct >> 4); // unit ct+64
    u64 s1 = 0ull, s2 = 0ull;
    const float* wp1 = Wd + (size_t)kb * OUT_N + 2 * cp1;
#pragma unroll 8
    for (int kk = 0; kk < KSH; kk++) {
        u64 w = *(const u64*)(wp1 + kk * OUT_N);
        const float* ap = buf + (kb + kk) * BST;
        s1 = fma2(dup2(ap[r1]), w, s1);
        s2 = fma2(dup2(ap[r2]), w, s2);
    }
    scr[kg * 128 + ct]      = s1;
    scr[kg * 128 + ct + 64] = s2;
}

// Reduce proj partials (tid<128): unit = tid, sum over 8 groups + bias.
__device__ __forceinline__ float2 proj_reduce(const u64* __restrict__ scr,
                                              u64 bd2, int unit)
{
    u64 v0 = scr[0 * 128 + unit], v1 = scr[1 * 128 + unit];
    u64 v2 = scr[2 * 128 + unit], v3 = scr[3 * 128 + unit];
    u64 v4 = scr[4 * 128 + unit], v5 = scr[5 * 128 + unit];
    u64 v6 = scr[6 * 128 + unit], v7 = scr[7 * 128 + unit];
    u64 s = add2(add2(add2(v0, v1), add2(v2, v3)),
                 add2(add2(v4, v5), add2(add2(v6, v7), bd2)));
    return unpk(s);
}

__global__ void __launch_bounds__(NTH, 1)
cde_kernel(const float* __restrict__ coeffs, const float* __restrict__ times,
           const float* __restrict__ Wi,     const float* __restrict__ bi,
           const float* __restrict__ Wf,     const float* __restrict__ bfb,
           const float* __restrict__ Wd,     const float* __restrict__ bd,
           float* __restrict__ out)
{
    extern __shared__ float smem[];
    float* bufA = smem;                                  // 2048 floats
    float* bufB = smem + BUF_FLOATS;                     // 2048 floats
    float* red  = smem + 2 * BUF_FLOATS;                 // 18432 floats
    u64*   scr  = (u64*)(smem + 2 * BUF_FLOATS + RED_FLOATS);  // 8x128 u64

    const int tid   = threadIdx.x;
    const int kg    = tid >> 6;                 // split-K group 0..7
    const int ct    = tid & 63;                 // column-thread in group
    const int n0    = ct * 4;
    const int bbase = blockIdx.x * MC;

    // combine/update mapping: thread owns column n_e, rows m0..m0+3.
    const int ct_e = tid >> 3;
    const int sub  = tid & 7;
    const int c_e  = sub >> 1;
    const int m0   = (sub & 1) * 4;
    const int n_e  = ct_e * 4 + c_e;
    const int off  = c_e * 8 + m0;

    float* redp = red + (kg * NCT + ct) * RST;
    u64 acc[16];
    float4 wA[4], wB[4];

    // loop-invariant scalars hoisted off the combine critical path
    const float bias0 = bfb[0 * H_N + n_e];
    const float bias1 = bfb[1 * H_N + n_e];
    const float bias2 = bfb[2 * H_N + n_e];
    const float bias3 = bfb[3 * H_N + n_e];

    // proj-reduce mapping (tid<128): unit = tid = r*16 + cp
    const u64 bd2  = *(const u64*)(bd + 2 * (tid & 15));
    float* outp    = out + (size_t)(bbase + ((tid & 127) >> 4)) * T_N * OUT_N
                         + 2 * (tid & 15);

    // per-thread weight base for the hidden layers
    const size_t HH = (size_t)H_N * H_N;
    const float* W0 = Wf + (size_t)kg * KSH * H_N + n0;
    const int kact  = kg * KSH * BST;           // act offset for hidden GEMMs

    // ---- stage coeffs[:,0,:] -> bufA[k][m] ----
    if (tid < 256) {
        int m = tid >> 5, kk = tid & 31;
        bufA[kk * BST + m] = coeffs[(size_t)(bbase + m) * T_N * IN_N + kk];
    }

    // preload init-GEMM weights (KSI=4: one block) while staging lands
    wpre<KSI>(Wi + (size_t)kg * KSI * H_N + n0, wA, wB);
    __syncthreads();            // full: coeffs staged cross-group

    // ---- y0 = coeffs0 @ Wi + bi ----
    float y[4], ksum[4];
    gemmT4<KSI>(Wi + (size_t)kg * KSI * H_N + n0, bufA + kg * KSI * BST, wA, wB, acc);
    red_put(redp, acc);
    wpre<KSH>(W0, wA, wB);                      // prefetch layer-0 weights
    __syncthreads();            // full: deposits cross all groups
    {
        float4 v = combine8(red, ct_e, off);
        float bb = bi[n_e];
        y[0] = v.x + bb; y[1] = v.y + bb; y[2] = v.z + bb; y[3] = v.w + bb;
        *(float4*)(bufA + n_e * BST + m0) = make_float4(y[0], y[1], y[2], y[3]);
    }
    gbar(kg);                   // group-local: st0/l0 GEMM+proj read own cols

    // ---- time loop; group-local proj of y_t folded into st0/l0 of step t ----
#pragma unroll 1
    for (int t = 0; t < T_N - 1; t++) {
        const float dt = times[t + 1] - times[t];

#pragma unroll 1
        for (int st = 0; st < 4; st++) {
            float* in = bufA; float* ob = bufB;
#pragma unroll 1
            for (int l = 0; l < 3; l++) {
                if (st == 0 && l == 0)
                    proj_partials(bufA, Wd, scr, kg, ct);   // own k-slice only
                gemmT4<KSH>(W0 + l * HH, in + kact, wA, wB, acc);
                red_put(redp, acc);
                wpre<KSH>(W0 + (l + 1) * HH, wA, wB);   // prefetch next layer
                __syncthreads();     // full: deposits cross all groups (+scr)
                if (st == 0 && l == 0 && tid < 128)
                    *(float2*)(outp + (size_t)t * OUT_N) = proj_reduce(scr, bd2, tid);
                float4 v = combine8(red, ct_e, off);
                float bb = (l == 0) ? bias0 : (l == 1) ? bias1 : bias2;
                v.x = lipswish(v.x + bb); v.y = lipswish(v.y + bb);
                v.z = lipswish(v.z + bb); v.w = lipswish(v.w + bb);
                *(float4*)(ob + n_e * BST + m0) = v;
                gbar(kg);            // group-local: own GEMM reads own columns
                float* tmp = in; in = ob; ob = tmp;
            }
            gemmT4<KSH>(W0 + 3 * HH, in + kact, wA, wB, acc);
            red_put(redp, acc);
            wpre<KSH>(W0, wA, wB);                      // prefetch next stage L0
            __syncthreads();         // full: deposits cross all groups
            float4 kv = combine8(red, ct_e, off);
            kv.x += bias3; kv.y += bias3; kv.z += bias3; kv.w += bias3;
            float k4[4] = {kv.x, kv.y, kv.z, kv.w};
            float s4[4];
            if (st == 0) {
#pragma unroll
                for (int i = 0; i < 4; i++) { ksum[i] = k4[i]; s4[i] = fmaf(0.5f * dt, k4[i], y[i]); }
            } else if (st == 1) {
#pragma unroll
                for (int i = 0; i < 4; i++) { ksum[i] = fmaf(2.f, k4[i], ksum[i]); s4[i] = fmaf(0.5f * dt, k4[i], y[i]); }
            } else if (st == 2) {
#pragma unroll
                for (int i = 0; i < 4; i++) { ksum[i] = fmaf(2.f, k4[i], ksum[i]); s4[i] = fmaf(dt, k4[i], y[i]); }
            } else {
#pragma unroll
                for (int i = 0; i < 4; i++) { ksum[i] += k4[i]; y[i] = fmaf(dt * (1.f / 6.f), ksum[i], y[i]); s4[i] = y[i]; }
            }
            *(float4*)(bufA + n_e * BST + m0) = make_float4(s4[0], s4[1], s4[2], s4[3]);
            gbar(kg);    // group-local: next st0/l0 GEMM + proj read own cols
        }
    }

    // ---- final projection of y_{T-1} (group-local k-slices) ----
    {
        proj_partials(bufA, Wd, scr, kg, ct);
        __syncthreads();
        if (tid < 128)
            *(float2*)(outp + (size_t)(T_N - 1) * OUT_N) = proj_reduce(scr, bd2, tid);
    }
}

extern "C" void kernel_launch(void* const* d_in, const int* in_sizes, int n_in,
                              void* d_out, int out_size)
{
    const float* coeffs = (const float*)d_in[0];
    const float* times  = (const float*)d_in[1];
    const float* Wi     = (const float*)d_in[2];
    const float* bi     = (const float*)d_in[3];
    const float* Wf     = (const float*)d_in[4];
    const float* bf     = (const float*)d_in[5];
    const float* Wd     = (const float*)d_in[6];
    const float* bd     = (const float*)d_in[7];
    float* out = (float*)d_out;

    cudaFuncSetAttribute(cde_kernel,
                         cudaFuncAttributeMaxDynamicSharedMemorySize, SMEM_BYTES);

    const int B    = in_sizes[0] / (T_N * IN_N);   // 1024
    const int grid = B / MC;                       // 128
    cde_kernel<<<grid, NTH, SMEM_BYTES>>>(coeffs, times, Wi, bi, Wf, bf, Wd, bd, out);
}

// round 13
// speedup vs baseline: 1.0423x; 1.0423x over previous
#include <cuda_runtime.h>
#include <cstdint>
#include <cstddef>

// Neural-CDE forward, R13 = R11 (best: 6.999ms) + fast lipswish ONLY.
// R12 decomposition: fdividef helped (~1%), group-local proj hurt (~1.5%) —
// so the proj restructure is reverted and only the validated MUFU.RCP
// lipswish is kept (rel_err 2.7e-7 confirmed in R12).
// Config: 128 CTAs x 512 thr, MC=8, 8-way split-K, 4 cols/thread,
// fma.rn.f32x2 GEMM core, exact weight loads, cross-GEMM weight prefetch,
// group-local act-ready barriers, packed-f32x2 tree combine, packed proj.

#define T_N   128
#define IN_N  32
#define H_N   256
#define OUT_N 32
#define MC    8            // batch rows per CTA
#define BST   8            // activation buffer stride [dim][row]
#define NTH   512
#define NG    8            // split-K groups
#define NCT   64           // column-threads per group (4 cols each)
#define KSH   (H_N / NG)   // 32
#define KSI   (IN_N / NG)  // 4
#define RST   36           // reduction stride in floats (32 data + 4 pad)

#define BUF_FLOATS   (H_N * BST)            // 2048
#define RED_FLOATS   (NG * NCT * RST)       // 18432
#define SCR_FLOATS   768                    // proj partials: 3 quarters x 128 u64
#define SMEM_FLOATS  (2 * BUF_FLOATS + RED_FLOATS + SCR_FLOATS)
#define SMEM_BYTES   (SMEM_FLOATS * 4)      // 93184

typedef unsigned long long u64;

__device__ __forceinline__ u64 fma2(u64 a, u64 b, u64 c) {
    u64 d;
    asm("fma.rn.f32x2 %0, %1, %2, %3;" : "=l"(d) : "l"(a), "l"(b), "l"(c));
    return d;
}
__device__ __forceinline__ u64 add2(u64 a, u64 b) {
    u64 d;
    asm("add.rn.f32x2 %0, %1, %2;" : "=l"(d) : "l"(a), "l"(b));
    return d;
}
__device__ __forceinline__ u64 dup2(float x) {
    u64 d; unsigned int u = __float_as_uint(x);
    asm("mov.b64 %0, {%1, %2};" : "=l"(d) : "r"(u), "r"(u));
    return d;
}
__device__ __forceinline__ float2 unpk(u64 v) {
    unsigned int a, b;
    asm("mov.b64 {%0, %1}, %2;" : "=r"(a), "=r"(b) : "l"(v));
    return make_float2(__uint_as_float(a), __uint_as_float(b));
}
__device__ __forceinline__ float lipswish(float x) {
    // 0.909*x*sigmoid(x); __fdividef -> MUFU.RCP (2-ulp; validated in R12)
    return __fdividef(0.909f * x, 1.0f + __expf(-x));
}
// 64-thread named barrier for split-K group kg (ids 1..8; 0 = __syncthreads).
__device__ __forceinline__ void gbar(int kg) {
    asm volatile("bar.sync %0, %1;" :: "r"(1 + kg), "r"(64) : "memory");
}

// Preload the first two 4-k-row weight blocks of a GEMM (guards compile out).
template <int KS>
__device__ __forceinline__ void wpre(const float* __restrict__ Wp,
                                     float4* __restrict__ wA,
                                     float4* __restrict__ wB)
{
#pragma unroll
    for (int j = 0; j < 4; j++) if (j < KS)     wA[j] = *(const float4*)(Wp + j * H_N);
#pragma unroll
    for (int j = 0; j < 4; j++) if (4 + j < KS) wB[j] = *(const float4*)(Wp + (4 + j) * H_N);
}

// Raw partial GEMM over KS k-rows, 4 columns, 8 rows. acc[c*4+p] packs rows
// (2p,2p+1) of local column c: p=0 -> ua.x, p=1 -> ua.y, p=2 -> ub.x,
// p=3 -> ub.y. Wp pre-offset to (koff, n0); bp pre-offset to koff. wA/wB hold
// the first two blocks (preloaded by caller before the previous barrier).
template <int KS>
__device__ __forceinline__ void gemmT4(const float* __restrict__ Wp,
                                       const float* __restrict__ bp,
                                       float4* __restrict__ wA,
                                       float4* __restrict__ wB,
                                       u64* __restrict__ acc)
{
#pragma unroll
    for (int i = 0; i < 16; i++) acc[i] = 0ull;

    ulonglong2 ua = *(const ulonglong2*)(bp);       // k-row 0: rows (0,1),(2,3)
    ulonglong2 ub = *(const ulonglong2*)(bp + 4);   //          rows (4,5),(6,7)

#pragma unroll
    for (int kb = 0; kb < KS; kb += 4) {
        float4 wN[4];
        const bool ldw = (kb + 8 < KS);
        if (ldw) {
#pragma unroll
            for (int j = 0; j < 4; j++) wN[j] = *(const float4*)(Wp + (kb + 8 + j) * H_N);
        }
#pragma unroll
        for (int j = 0; j < 4; j++) {
            if (kb + j >= KS) continue;                    // compile-time (KS=4 case)
            const int knext = kb + j + 1;
            ulonglong2 na, nb;
            const bool lda = (knext < KS);
            if (lda) {
                na = *(const ulonglong2*)(bp + knext * BST);
                nb = *(const ulonglong2*)(bp + knext * BST + 4);
            }
            u64 w0 = dup2(wA[j].x), w1 = dup2(wA[j].y);
            u64 w2 = dup2(wA[j].z), w3 = dup2(wA[j].w);
            acc[0]  = fma2(ua.x, w0, acc[0]);  acc[1]  = fma2(ua.y, w0, acc[1]);
            acc[2]  = fma2(ub.x, w0, acc[2]);  acc[3]  = fma2(ub.y, w0, acc[3]);
            acc[4]  = fma2(ua.x, w1, acc[4]);  acc[5]  = fma2(ua.y, w1, acc[5]);
            acc[6]  = fma2(ub.x, w1, acc[6]);  acc[7]  = fma2(ub.y, w1, acc[7]);
            acc[8]  = fma2(ua.x, w2, acc[8]);  acc[9]  = fma2(ua.y, w2, acc[9]);
            acc[10] = fma2(ub.x, w2, acc[10]); acc[11] = fma2(ub.y, w2, acc[11]);
            acc[12] = fma2(ua.x, w3, acc[12]); acc[13] = fma2(ua.y, w3, acc[13]);
            acc[14] = fma2(ub.x, w3, acc[14]); acc[15] = fma2(ub.y, w3, acc[15]);
            if (lda) { ua = na; ub = nb; }
        }
#pragma unroll
        for (int j = 0; j < 4; j++) wA[j] = wB[j];
        if (ldw) {
#pragma unroll
            for (int j = 0; j < 4; j++) wB[j] = wN[j];
        }
    }
}

// Deposit 32 raw floats (16 packed pairs) at redp: word layout c*8+m.
__device__ __forceinline__ void red_put(float* __restrict__ redp,
                                        const u64* __restrict__ acc)
{
#pragma unroll
    for (int c = 0; c < 4; c++) {
        *(ulonglong2*)(redp + c * 8)     = make_ulonglong2(acc[c * 4],     acc[c * 4 + 1]);
        *(ulonglong2*)(redp + c * 8 + 4) = make_ulonglong2(acc[c * 4 + 2], acc[c * 4 + 3]);
    }
}

// Sum the 8 group-partials for this thread's float4 via a packed-f32x2 tree.
__device__ __forceinline__ float4 combine8(const float* __restrict__ red,
                                           int ct_e, int off)
{
    const float* p = red + ct_e * RST + off;
    ulonglong2 v0 = *(const ulonglong2*)(p);
    ulonglong2 v1 = *(const ulonglong2*)(p + 1 * NCT * RST);
    ulonglong2 v2 = *(const ulonglong2*)(p + 2 * NCT * RST);
    ulonglong2 v3 = *(const ulonglong2*)(p + 3 * NCT * RST);
    ulonglong2 v4 = *(const ulonglong2*)(p + 4 * NCT * RST);
    ulonglong2 v5 = *(const ulonglong2*)(p + 5 * NCT * RST);
    ulonglong2 v6 = *(const ulonglong2*)(p + 6 * NCT * RST);
    ulonglong2 v7 = *(const ulonglong2*)(p + 7 * NCT * RST);
    u64 ax = add2(add2(add2(v0.x, v1.x), add2(v2.x, v3.x)),
                  add2(add2(v4.x, v5.x), add2(v6.x, v7.x)));
    u64 ay = add2(add2(add2(v0.y, v1.y), add2(v2.y, v3.y)),
                  add2(add2(v4.y, v5.y), add2(v6.y, v7.y)));
    float2 lo = unpk(ax), hi = unpk(ay);
    return make_float4(lo.x, lo.y, hi.x, hi.y);
}

// Packed projection partial over one K-quarter: 2 output columns per thread.
__device__ __forceinline__ u64 proj_part2(const float* __restrict__ buf,
                                          const float* __restrict__ Wd,
                                          u64 bd2, int q, int r, int cp)
{
    u64 s2 = (q == 0) ? bd2 : 0ull;
    const int k0 = q * (H_N / 4);
    const float* wp = Wd + 2 * cp;
#pragma unroll 8
    for (int kk = k0; kk < k0 + H_N / 4; kk++) {
        u64 w = *(const u64*)(wp + kk * OUT_N);
        s2 = fma2(dup2(buf[kk * BST + r]), w, s2);
    }
    return s2;
}

__global__ void __launch_bounds__(NTH, 1)
cde_kernel(const float* __restrict__ coeffs, const float* __restrict__ times,
           const float* __restrict__ Wi,     const float* __restrict__ bi,
           const float* __restrict__ Wf,     const float* __restrict__ bfb,
           const float* __restrict__ Wd,     const float* __restrict__ bd,
           float* __restrict__ out)
{
    extern __shared__ float smem[];
    float* bufA = smem;                                  // 2048 floats
    float* bufB = smem + BUF_FLOATS;                     // 2048 floats
    float* red  = smem + 2 * BUF_FLOATS;                 // 18432 floats
    u64*   scr  = (u64*)(smem + 2 * BUF_FLOATS + RED_FLOATS);  // 3*128 u64

    const int tid   = threadIdx.x;
    const int kg    = tid >> 6;                 // split-K group 0..7
    const int ct    = tid & 63;                 // column-thread in group
    const int n0    = ct * 4;
    const int bbase = blockIdx.x * MC;

    // combine/update mapping: thread owns column n_e, rows m0..m0+3.
    const int ct_e = tid >> 3;
    const int sub  = tid & 7;
    const int c_e  = sub >> 1;
    const int m0   = (sub & 1) * 4;
    const int n_e  = ct_e * 4 + c_e;
    const int off  = c_e * 8 + m0;

    // projection mapping: 128 units (8 rows x 16 col-pairs) x 4 K-quarters
    const int p_q    = tid >> 7;                // K-quarter 0..3
    const int p_unit = tid & 127;
    const int p_r    = p_unit >> 4;             // batch row 0..7
    const int p_cp   = p_unit & 15;             // col-pair 0..15

    float* redp = red + (kg * NCT + ct) * RST;
    u64 acc[16];
    float4 wA[4], wB[4];

    // loop-invariant scalars hoisted off the combine critical path
    const float bias0 = bfb[0 * H_N + n_e];
    const float bias1 = bfb[1 * H_N + n_e];
    const float bias2 = bfb[2 * H_N + n_e];
    const float bias3 = bfb[3 * H_N + n_e];
    const u64   bd2   = *(const u64*)(bd + 2 * p_cp);

    // per-thread weight base for the hidden layers
    const size_t HH = (size_t)H_N * H_N;
    const float* W0 = Wf + (size_t)kg * KSH * H_N + n0;
    const int kact  = kg * KSH * BST;           // act offset for hidden GEMMs

    // hoisted output base for this thread's projection writes
    float* outp = out + (size_t)(bbase + p_r) * T_N * OUT_N + 2 * p_cp;

    // ---- stage coeffs[:,0,:] -> bufA[k][m] ----
    if (tid < 256) {
        int m = tid >> 5, kk = tid & 31;
        bufA[kk * BST + m] = coeffs[(size_t)(bbase + m) * T_N * IN_N + kk];
    }

    // preload init-GEMM weights (KSI=4: one block) while staging lands
    wpre<KSI>(Wi + (size_t)kg * KSI * H_N + n0, wA, wB);
    __syncthreads();

    // ---- y0 = coeffs0 @ Wi + bi ----
    float y[4], ksum[4];
    gemmT4<KSI>(Wi + (size_t)kg * KSI * H_N + n0, bufA + kg * KSI * BST, wA, wB, acc);
    red_put(redp, acc);
    wpre<KSH>(W0, wA, wB);                      // prefetch layer-0 weights
    __syncthreads();
    {
        float4 v = combine8(red, ct_e, off);
        float bb = bi[n_e];
        y[0] = v.x + bb; y[1] = v.y + bb; y[2] = v.z + bb; y[3] = v.w + bb;
        *(float4*)(bufA + n_e * BST + m0) = make_float4(y[0], y[1], y[2], y[3]);
    }
    __syncthreads();            // full: next proj (st0/l0) reads ALL columns

    // ---- time loop; proj of y_t folded into stage-0/layer-0 of step t ----
#pragma unroll 1
    for (int t = 0; t < T_N - 1; t++) {
        const float dt = times[t + 1] - times[t];

#pragma unroll 1
        for (int st = 0; st < 4; st++) {
            float* in = bufA; float* ob = bufB;
            u64 ps2 = 0ull;
#pragma unroll 1
            for (int l = 0; l < 3; l++) {
                if (st == 0 && l == 0) {
                    // projection partial of y_t (bufA stable through this GEMM)
                    ps2 = proj_part2(bufA, Wd, bd2, p_q, p_r, p_cp);
                    if (p_q) scr[(p_q - 1) * 128 + p_unit] = ps2;
                }
                gemmT4<KSH>(W0 + l * HH, in + kact, wA, wB, acc);
                red_put(redp, acc);
                wpre<KSH>(W0 + (l + 1) * HH, wA, wB);   // prefetch next layer
                __syncthreads();     // full: deposits cross all groups (+scr)
                if (st == 0 && l == 0 && p_q == 0) {
                    u64 s = add2(add2(ps2, scr[p_unit]),
                                 add2(scr[128 + p_unit], scr[256 + p_unit]));
                    *(float2*)(outp + (size_t)t * OUT_N) = unpk(s);
                }
                float4 v = combine8(red, ct_e, off);
                float bb = (l == 0) ? bias0 : (l == 1) ? bias1 : bias2;
                v.x = lipswish(v.x + bb); v.y = lipswish(v.y + bb);
                v.z = lipswish(v.z + bb); v.w = lipswish(v.w + bb);
                *(float4*)(ob + n_e * BST + m0) = v;
                gbar(kg);            // group-local: own GEMM reads own columns
                float* tmp = in; in = ob; ob = tmp;
            }
            gemmT4<KSH>(W0 + 3 * HH, in + kact, wA, wB, acc);
            red_put(redp, acc);
            wpre<KSH>(W0, wA, wB);                      // prefetch next stage L0
            __syncthreads();         // full: deposits cross all groups
            float4 kv = combine8(red, ct_e, off);
            kv.x += bias3; kv.y += bias3; kv.z += bias3; kv.w += bias3;
            float k4[4] = {kv.x, kv.y, kv.z, kv.w};
            float s4[4];
            if (st == 0) {
#pragma unroll
                for (int i = 0; i < 4; i++) { ksum[i] = k4[i]; s4[i] = fmaf(0.5f * dt, k4[i], y[i]); }
            } else if (st == 1) {
#pragma unroll
                for (int i = 0; i < 4; i++) { ksum[i] = fmaf(2.f, k4[i], ksum[i]); s4[i] = fmaf(0.5f * dt, k4[i], y[i]); }
            } else if (st == 2) {
#pragma unroll
                for (int i = 0; i < 4; i++) { ksum[i] = fmaf(2.f, k4[i], ksum[i]); s4[i] = fmaf(dt, k4[i], y[i]); }
            } else {
#pragma unroll
                for (int i = 0; i < 4; i++) { ksum[i] += k4[i]; y[i] = fmaf(dt * (1.f / 6.f), ksum[i], y[i]); s4[i] = y[i]; }
            }
            *(float4*)(bufA + n_e * BST + m0) = make_float4(s4[0], s4[1], s4[2], s4[3]);
            if (st < 3) gbar(kg);    // group-local: next stage L0 reads own cols
            else        __syncthreads();   // full: st0/l0 proj reads ALL columns
        }
    }

    // ---- final projection of y_{T-1} ----
    {
        u64 ps2 = proj_part2(bufA, Wd, bd2, p_q, p_r, p_cp);
        if (p_q) scr[(p_q - 1) * 128 + p_unit] = ps2;
        __syncthreads();
        if (p_q == 0) {
            u64 s = add2(add2(ps2, scr[p_unit]),
                         add2(scr[128 + p_unit], scr[256 + p_unit]));
            *(float2*)(outp + (size_t)(T_N - 1) * OUT_N) = unpk(s);
        }
    }
}

extern "C" void kernel_launch(void* const* d_in, const int* in_sizes, int n_in,
                              void* d_out, int out_size)
{
    const float* coeffs = (const float*)d_in[0];
    const float* times  = (const float*)d_in[1];
    const float* Wi     = (const float*)d_in[2];
    const float* bi     = (const float*)d_in[3];
    const float* Wf     = (const float*)d_in[4];
    const float* bf     = (const float*)d_in[5];
    const float* Wd     = (const float*)d_in[6];
    const float* bd     = (const float*)d_in[7];
    float* out = (float*)d_out;

    cudaFuncSetAttribute(cde_kernel,
                         cudaFuncAttributeMaxDynamicSharedMemorySize, SMEM_BYTES);

    const int B    = in_sizes[0] / (T_N * IN_N);   // 1024
    const int grid = B / MC;                       // 128
    cde_kernel<<<grid, NTH, SMEM_BYTES>>>(coeffs, times, Wi, bi, Wf, bf, Wd, bd, out);
}